// round 1
// baseline (speedup 1.0000x reference)
#include <cuda_runtime.h>

#define BB 8
#define NN 2048
#define CC 128
#define HH 4
#define DD 32
#define SS 3
#define KNB 16
#define KT 48
#define PP 8   // points per block in attn kernel

__device__ int   g_knn[BB * NN * KT];
__device__ float g_WkT[SS * CC * CC];

// ---------------------------------------------------------------------------
// Kernel 0: transpose Wk so qk projection reads coalesced.
// WkT[i][j][c] = Wk[i][c][j]
// ---------------------------------------------------------------------------
__global__ void transpose_wk_kernel(const float* __restrict__ Wk) {
    int i = blockIdx.y;
    int idx = blockIdx.x * blockDim.x + threadIdx.x;   // 0..16383
    int c = idx >> 7, j = idx & 127;
    g_WkT[i * CC * CC + j * CC + c] = Wk[i * CC * CC + c * CC + j];
}

// ---------------------------------------------------------------------------
// Kernel 1: exact kNN top-48 (sorted ascending by (dist, idx)) per query.
// One warp per query; per-lane min-heap of 64 candidates in local memory.
// Key packs monotone float bits in high 32, index in low 32 -> u64 compare
// == lexicographic (dist, idx), matching jax.lax.top_k tie semantics.
// ---------------------------------------------------------------------------
__device__ __forceinline__ void heap_sift(unsigned long long* h, int size, int p) {
    unsigned long long v = h[p];
    while (true) {
        int c = 2 * p + 1;
        if (c >= size) break;
        unsigned long long cv = h[c];
        if (c + 1 < size) {
            unsigned long long cv2 = h[c + 1];
            if (cv2 < cv) { cv = cv2; c++; }
        }
        if (cv < v) { h[p] = cv; p = c; } else break;
    }
    h[p] = v;
}

__global__ __launch_bounds__(256) void knn_kernel(const float* __restrict__ coord) {
    __shared__ float sx[NN], sy[NN], sz[NN], sq[NN];
    const int t = threadIdx.x;
    const int lane = t & 31, w = t >> 5;
    const int b = blockIdx.x / (NN / 8);
    const int n0 = (blockIdx.x % (NN / 8)) * 8;
    const float* cb = coord + (size_t)b * NN * 3;

    for (int j = t; j < NN; j += 256) {
        float x = cb[j * 3], y = cb[j * 3 + 1], z = cb[j * 3 + 2];
        sx[j] = x; sy[j] = y; sz[j] = z;
        sq[j] = fmaf(x, x, fmaf(y, y, z * z));
    }
    __syncthreads();

    const int n = n0 + w;
    const float ox = sx[n], oy = sy[n], oz = sz[n], osq = sq[n];

    unsigned long long h[64];
    #pragma unroll 4
    for (int s = 0; s < 64; s++) {
        int j = lane + (s << 5);
        float dot = fmaf(ox, sx[j], fmaf(oy, sy[j], oz * sz[j]));
        float d = fmaf(-2.0f, dot, osq + sq[j]);   // matches ref: sq_n + sq_m - 2*dot
        unsigned u = __float_as_uint(d);
        u = (u & 0x80000000u) ? ~u : (u | 0x80000000u);  // monotone total order
        h[s] = ((unsigned long long)u << 32) | (unsigned)j;
    }
    for (int i = 31; i >= 0; i--) heap_sift(h, 64, i);

    int size = 64;
    unsigned long long root = h[0];
    int* outp = g_knn + ((size_t)b * NN + n) * KT;

    for (int r = 0; r < KT; r++) {
        unsigned long long m = root;
        #pragma unroll
        for (int off = 16; off; off >>= 1) {
            unsigned long long o = __shfl_xor_sync(0xffffffffu, m, off);
            if (o < m) m = o;
        }
        if (root == m) {           // unique winner (indices distinct)
            size--;
            h[0] = h[size];
            heap_sift(h, size, 0);
            root = h[0];
        }
        if (lane == 0) outp[r] = (int)(m & 0xffffffffu);
    }
}

// ---------------------------------------------------------------------------
// Kernel 2: fused projections + attention.
// 8 points per 128-thread block. Per scale i:
//   qk[p][h][c] = sum_d q[p][h*32+d] * WkT[i][h*32+d][c]      (coalesced)
//   logit[p][h][k] = inv * (nbr_k . qk - pcd_n . qk + q . bk[i])
//   softmax over 16, attn[p][h] += sum a*logit
// out[p][c] = attn[p][c/32] * v[p][c]
// ---------------------------------------------------------------------------
__global__ __launch_bounds__(128) void attn_kernel(
    const float* __restrict__ pcd,
    const float* __restrict__ Wq, const float* __restrict__ bq,
    const float* __restrict__ bk,
    const float* __restrict__ Wv, const float* __restrict__ bv,
    float* __restrict__ out)
{
    __shared__ float s_pcd[PP][CC];
    __shared__ float s_q[PP][CC];
    __shared__ float s_v[PP][CC];
    __shared__ float s_qk[PP][HH][CC + 4];    // one scale at a time, padded rows
    __shared__ float s_logit[PP][HH][KNB];
    __shared__ float s_nbr[4][CC];            // one buffer per warp
    __shared__ float s_attn[PP][HH];

    const int t = threadIdx.x;
    const int lane = t & 31, w = t >> 5;
    const int b = blockIdx.x / (NN / PP);
    const int n0 = (blockIdx.x % (NN / PP)) * PP;
    const float* pb = pcd + (size_t)b * NN * CC;

    #pragma unroll
    for (int p = 0; p < PP; p++) s_pcd[p][t] = pb[(size_t)(n0 + p) * CC + t];
    __syncthreads();

    // --- q, v projections: thread t owns output column t for all 8 points ---
    {
        float aq[PP], av[PP];
        #pragma unroll
        for (int p = 0; p < PP; p++) { aq[p] = 0.0f; av[p] = 0.0f; }
        #pragma unroll 4
        for (int c = 0; c < CC; c++) {
            float wq = Wq[c * CC + t];
            float wv = Wv[c * CC + t];
            #pragma unroll
            for (int p = 0; p < PP; p++) {
                float x = s_pcd[p][c];
                aq[p] = fmaf(x, wq, aq[p]);
                av[p] = fmaf(x, wv, av[p]);
            }
        }
        float b1 = bq[t], b2 = bv[t];
        #pragma unroll
        for (int p = 0; p < PP; p++) {
            s_q[p][t] = aq[p] + b1;
            s_v[p][t] = av[p] + b2;
        }
    }
    __syncthreads();

    float attn_acc[PP / 4];   // t<32 threads accumulate (p = t>>2, h = t&3); others unused
    // (only valid on t<32; use full array of 2 to keep it simple: p index via t>>2 below)
    float acc_attn = 0.0f;    // for t < 32: accumulates over scales for (p=t>>2, h=t&3)
    (void)attn_acc;

    const float inv = 0.17677669529663687f;   // 1/sqrt(32)

    for (int i = 0; i < SS; i++) {
        // --- qk projection: warp w owns columns c = w*32 + lane ---
        {
            const int c = (w << 5) | lane;
            float acc[PP][HH];
            #pragma unroll
            for (int p = 0; p < PP; p++)
                #pragma unroll
                for (int hh = 0; hh < HH; hh++) acc[p][hh] = 0.0f;
            const float* wkt = g_WkT + i * CC * CC + c;
            #pragma unroll
            for (int j = 0; j < CC; j++) {
                float wv_ = wkt[j * CC];       // coalesced: lane-contiguous
                const int hh = j >> 5;         // compile-time after full unroll
                #pragma unroll
                for (int p = 0; p < PP; p++)
                    acc[p][hh] = fmaf(s_q[p][j], wv_, acc[p][hh]);
            }
            #pragma unroll
            for (int p = 0; p < PP; p++)
                #pragma unroll
                for (int hh = 0; hh < HH; hh++)
                    s_qk[p][hh][c] = acc[p][hh];
        }
        __syncthreads();

        // --- logits: warp w handles points 2w and 2w+1, 16 neighbors each ---
        {
            const int hh = lane & 3, cg = lane >> 2;
            const int c0 = cg * 16;
            #pragma unroll
            for (int pp = 0; pp < 2; pp++) {
                const int p = 2 * w + pp;
                const int* kn = g_knn + ((size_t)b * NN + n0 + p) * KT + i * KNB;
                const float* qkp = s_qk[p][hh];
                for (int k = 0; k < KNB; k++) {
                    int j = kn[k];                                   // uniform load
                    float4 nv = ((const float4*)(pb + (size_t)j * CC))[lane];
                    ((float4*)s_nbr[w])[lane] = nv;
                    __syncwarp();
                    float s = 0.0f;
                    #pragma unroll
                    for (int m = 0; m < 4; m++) {
                        float4 a4 = *(const float4*)(qkp + c0 + 4 * m);
                        float4 b4 = *(const float4*)(s_nbr[w] + c0 + 4 * m);
                        s = fmaf(a4.x, b4.x, s);
                        s = fmaf(a4.y, b4.y, s);
                        s = fmaf(a4.z, b4.z, s);
                        s = fmaf(a4.w, b4.w, s);
                    }
                    s += __shfl_xor_sync(0xffffffffu, s, 4);
                    s += __shfl_xor_sync(0xffffffffu, s, 8);
                    s += __shfl_xor_sync(0xffffffffu, s, 16);
                    if (cg == 0) s_logit[p][hh][k] = s;
                    __syncwarp();
                }
            }
        }
        __syncthreads();

        // --- own-dot, q.bk, softmax: t<32 owns (p = t>>2, h = t&3) ---
        if (t < PP * HH) {
            const int p = t >> 2, hh = t & 3;
            const float* qkp = s_qk[p][hh];
            float own = 0.0f;
            #pragma unroll 8
            for (int c = 0; c < CC; c++) own = fmaf(s_pcd[p][c], qkp[c], own);
            float qb = 0.0f;
            const float* bki = bk + i * CC + hh * DD;
            const float* qp = s_q[p] + hh * DD;
            #pragma unroll
            for (int d = 0; d < DD; d++) qb = fmaf(qp[d], bki[d], qb);

            float l[KNB];
            float mx = -1e30f;
            #pragma unroll
            for (int k = 0; k < KNB; k++) {
                l[k] = inv * (s_logit[p][hh][k] - own + qb);
                mx = fmaxf(mx, l[k]);
            }
            float se = 0.0f, sl = 0.0f;
            #pragma unroll
            for (int k = 0; k < KNB; k++) {
                float e = __expf(l[k] - mx);
                se += e;
                sl = fmaf(e, l[k], sl);
            }
            acc_attn += sl / se;
        }
        __syncthreads();   // protect s_qk / s_logit before next scale overwrites
    }

    if (t < PP * HH) s_attn[t >> 2][t & 3] = acc_attn;
    __syncthreads();

    #pragma unroll
    for (int p = 0; p < PP; p++)
        out[((size_t)b * NN + n0 + p) * CC + t] = s_attn[p][t >> 5] * s_v[p][t];
}

// ---------------------------------------------------------------------------
extern "C" void kernel_launch(void* const* d_in, const int* in_sizes, int n_in,
                              void* d_out, int out_size) {
    (void)in_sizes; (void)n_in; (void)out_size;
    const float* pcd   = (const float*)d_in[0];
    const float* coord = (const float*)d_in[1];
    // d_in[2] is K (=16), compile-time constant here
    const float* Wq    = (const float*)d_in[3];
    const float* bq    = (const float*)d_in[4];
    const float* Wk    = (const float*)d_in[5];
    const float* bk    = (const float*)d_in[6];
    const float* Wv    = (const float*)d_in[7];
    const float* bv    = (const float*)d_in[8];
    float* out = (float*)d_out;

    transpose_wk_kernel<<<dim3(CC * CC / 128, SS), 128>>>(Wk);
    knn_kernel<<<BB * NN / 8, 256>>>(coord);
    attn_kernel<<<BB * NN / PP, 128>>>(pcd, Wq, bq, bk, Wv, bv, out);
}

// round 2
// speedup vs baseline: 2.2196x; 2.2196x over previous
#include <cuda_runtime.h>

#define BB 8
#define NN 2048
#define CC 128
#define HH 4
#define DD 32
#define SS 3
#define KNB 16
#define KT 48
#define PP 16
#define QKPAD 136

#define FULLMASK 0xffffffffu

__device__ int   g_knn[BB * NN * KT];
__device__ float g_WkT[SS * CC * CC];

// ---------------------------------------------------------------------------
// Kernel 0: transpose Wk.  WkT[i][j][c] = Wk[i][c][j]
// ---------------------------------------------------------------------------
__global__ void transpose_wk_kernel(const float* __restrict__ Wk) {
    int i = blockIdx.y;
    int idx = blockIdx.x * blockDim.x + threadIdx.x;
    int c = idx >> 7, j = idx & 127;
    g_WkT[i * CC * CC + j * CC + c] = Wk[i * CC * CC + c * CC + j];
}

// ---------------------------------------------------------------------------
// Kernel 1: exact top-48 kNN per query, no local memory.
// One warp per query. 64 u32 monotone dist keys per lane in registers.
// (1) binary search for the 48th-smallest key (32 iters, REDUX per iter)
// (2) ballot-collect all keys <= T into smem (sorted by index)
// (3) warp bitonic sort of 64 u64 (key,idx) -> exact (dist, idx) order
// ---------------------------------------------------------------------------
__global__ __launch_bounds__(256) void knn_kernel(const float* __restrict__ coord) {
    __shared__ float sx[NN], sy[NN], sz[NN], sq[NN];
    __shared__ unsigned long long s_buf[8][64];

    const int t = threadIdx.x;
    const int lane = t & 31, w = t >> 5;
    const int b = blockIdx.x / (NN / 8);
    const int n0 = (blockIdx.x % (NN / 8)) * 8;
    const float* cb = coord + (size_t)b * NN * 3;

    for (int j = t; j < NN; j += 256) {
        float x = cb[j * 3], y = cb[j * 3 + 1], z = cb[j * 3 + 2];
        sx[j] = x; sy[j] = y; sz[j] = z;
        sq[j] = fmaf(x, x, fmaf(y, y, z * z));
    }
    __syncthreads();

    const int n = n0 + w;
    const float ox = sx[n], oy = sy[n], oz = sz[n], osq = sq[n];

    unsigned kkey[64];
    #pragma unroll
    for (int s = 0; s < 64; s++) {
        int j = lane + (s << 5);
        float dot = fmaf(ox, sx[j], fmaf(oy, sy[j], oz * sz[j]));
        float d = fmaf(-2.0f, dot, osq + sq[j]);   // matches reference formula
        unsigned u = __float_as_uint(d);
        u = (u & 0x80000000u) ? ~u : (u | 0x80000000u);  // monotone total order
        kkey[s] = u;
    }

    // ---- binary search for threshold T = 48th smallest key ----
    unsigned lo = 0u, hi = 0xffffffffu;
    for (int it = 0; it < 32; it++) {
        unsigned mid = lo + ((hi - lo) >> 1);
        unsigned c = 0;
        #pragma unroll
        for (int s = 0; s < 64; s++) c += (kkey[s] <= mid) ? 1u : 0u;
        c = __reduce_add_sync(FULLMASK, c);
        if (c >= KT) hi = mid; else lo = mid + 1;
        if (lo >= hi) break;     // warp-uniform
    }
    const unsigned T = lo;

    // ---- collect all candidates with key <= T (order: by index) ----
    s_buf[w][lane] = ~0ull;
    s_buf[w][lane + 32] = ~0ull;
    __syncwarp();
    int base = 0;
    #pragma unroll
    for (int s = 0; s < 64; s++) {
        bool q = (kkey[s] <= T);
        unsigned m = __ballot_sync(FULLMASK, q);
        if (q) {
            int pos = base + __popc(m & ((1u << lane) - 1u));
            if (pos < 64)
                s_buf[w][pos] = ((unsigned long long)kkey[s] << 32) |
                                (unsigned)(lane + (s << 5));
        }
        base += __popc(m);
    }
    __syncwarp();

    // ---- bitonic sort of 64 u64 keys, 2 per lane (i0 = lane, i1 = lane+32) ----
    unsigned long long v0 = s_buf[w][lane];
    unsigned long long v1 = s_buf[w][lane + 32];
    #pragma unroll
    for (int k2 = 2; k2 <= 64; k2 <<= 1) {
        #pragma unroll
        for (int j2 = k2 >> 1; j2 > 0; j2 >>= 1) {
            if (j2 == 32) {
                // only k2 == 64: both elements ascending
                unsigned long long a = v0 < v1 ? v0 : v1;
                unsigned long long bm = v0 < v1 ? v1 : v0;
                v0 = a; v1 = bm;
            } else {
                bool low = ((lane & j2) == 0);
                bool up0 = ((lane & k2) == 0);
                bool up1 = (((lane + 32) & k2) == 0);
                unsigned long long o0 = __shfl_xor_sync(FULLMASK, v0, j2);
                unsigned long long o1 = __shfl_xor_sync(FULLMASK, v1, j2);
                bool t0 = (low == up0);
                bool t1 = (low == up1);
                v0 = t0 ? (v0 < o0 ? v0 : o0) : (v0 > o0 ? v0 : o0);
                v1 = t1 ? (v1 < o1 ? v1 : o1) : (v1 > o1 ? v1 : o1);
            }
        }
    }

    int* outp = g_knn + ((size_t)b * NN + n) * KT;
    outp[lane] = (int)(v0 & 0xffffffffu);
    if (lane < KT - 32) outp[32 + lane] = (int)(v1 & 0xffffffffu);
}

// ---------------------------------------------------------------------------
// Kernel 2: fused projections + attention (16 points / 256-thread block).
// ---------------------------------------------------------------------------
struct AttnSmem {
    float pcd[PP][CC];
    float q[PP][CC];
    float v[PP][CC];
    float qk[PP][HH][QKPAD];
    float logit[PP][HH][KT];
    float own[PP][HH][SS];
    float attn[PP][HH];
};

// nb (4 cols of a row, this lane) dotted against 4 qk head-rows; staged
// butterfly reduce produces all 4 head sums; lanes 0,4,8,12 store them.
__device__ __forceinline__ void dot4_reduce_store(
    float4 nb, const float4* fq, float* dst, int strideH, int lane)
{
    float s0 = fmaf(nb.x, fq[0].x, fmaf(nb.y, fq[0].y, fmaf(nb.z, fq[0].z, nb.w * fq[0].w)));
    float s1 = fmaf(nb.x, fq[1].x, fmaf(nb.y, fq[1].y, fmaf(nb.z, fq[1].z, nb.w * fq[1].w)));
    float s2 = fmaf(nb.x, fq[2].x, fmaf(nb.y, fq[2].y, fmaf(nb.z, fq[2].z, nb.w * fq[2].w)));
    float s3 = fmaf(nb.x, fq[3].x, fmaf(nb.y, fq[3].y, fmaf(nb.z, fq[3].z, nb.w * fq[3].w)));
    #pragma unroll
    for (int off = 16; off >= 4; off >>= 1) {
        s0 += __shfl_xor_sync(FULLMASK, s0, off);
        s1 += __shfl_xor_sync(FULLMASK, s1, off);
        s2 += __shfl_xor_sync(FULLMASK, s2, off);
        s3 += __shfl_xor_sync(FULLMASK, s3, off);
    }
    // lane L now holds partials over cols with (col>>2) ≡ L&3 (mod 4)
    int hsel = (lane >> 2) & 3;
    float v = (hsel == 0) ? s0 : (hsel == 1) ? s1 : (hsel == 2) ? s2 : s3;
    v += __shfl_xor_sync(FULLMASK, v, 1);
    v += __shfl_xor_sync(FULLMASK, v, 2);
    if (lane < 16 && (lane & 3) == 0) dst[hsel * strideH] = v;
}

__global__ __launch_bounds__(256) void attn_kernel(
    const float* __restrict__ pcd,
    const float* __restrict__ Wq, const float* __restrict__ bq,
    const float* __restrict__ bk,
    const float* __restrict__ Wv, const float* __restrict__ bv,
    float* __restrict__ out)
{
    extern __shared__ char smem_raw[];
    AttnSmem* S = (AttnSmem*)smem_raw;

    const int t = threadIdx.x;
    const int lane = t & 31, w = t >> 5;
    const int col = t & 127, half = t >> 7;
    const int b = blockIdx.x / (NN / PP);
    const int n0 = (blockIdx.x % (NN / PP)) * PP;
    const float* pb = pcd + (size_t)b * NN * CC;

    for (int idx = t; idx < PP * CC; idx += 256) {
        int p = idx >> 7, c = idx & 127;
        S->pcd[p][c] = pb[(size_t)(n0 + p) * CC + c];
    }
    __syncthreads();

    // --- q, v projections: thread owns (col, half*8..half*8+7) ---
    {
        float aq[8], av[8];
        #pragma unroll
        for (int p = 0; p < 8; p++) { aq[p] = 0.0f; av[p] = 0.0f; }
        #pragma unroll 4
        for (int j = 0; j < CC; j++) {
            float wq = Wq[j * CC + col];
            float wv = Wv[j * CC + col];
            #pragma unroll
            for (int p = 0; p < 8; p++) {
                float x = S->pcd[half * 8 + p][j];
                aq[p] = fmaf(x, wq, aq[p]);
                av[p] = fmaf(x, wv, av[p]);
            }
        }
        float b1 = bq[col], b2 = bv[col];
        #pragma unroll
        for (int p = 0; p < 8; p++) {
            S->q[half * 8 + p][col] = aq[p] + b1;
            S->v[half * 8 + p][col] = av[p] + b2;
        }
    }
    __syncthreads();

    #pragma unroll 1
    for (int i = 0; i < SS; i++) {
        // --- qk projection: qk[p][h][col] = sum_{j in head h} q[p][j]*Wk[i][col][j]
        {
            const float* wkt = g_WkT + i * CC * CC + col;
            float acc[8][HH];
            #pragma unroll
            for (int p = 0; p < 8; p++)
                #pragma unroll
                for (int h = 0; h < HH; h++) acc[p][h] = 0.0f;
            #pragma unroll
            for (int j = 0; j < CC; j++) {
                float wv_ = wkt[j * CC];
                const int hh = j >> 5;
                #pragma unroll
                for (int p = 0; p < 8; p++)
                    acc[p][hh] = fmaf(S->q[half * 8 + p][j], wv_, acc[p][hh]);
            }
            #pragma unroll
            for (int p = 0; p < 8; p++)
                #pragma unroll
                for (int h = 0; h < HH; h++)
                    S->qk[half * 8 + p][h][col] = acc[p][h];
        }
        __syncthreads();

        // --- logits: warp w handles points 2w, 2w+1; fully parallel gather ---
        #pragma unroll
        for (int pp = 0; pp < 2; pp++) {
            const int p = 2 * w + pp;
            const int* kn = g_knn + ((size_t)b * NN + n0 + p) * KT + i * KNB;
            int myidx = (lane < KNB) ? kn[lane] : 0;
            float4 fq[4];
            #pragma unroll
            for (int h = 0; h < HH; h++)
                fq[h] = *(const float4*)&S->qk[p][h][4 * lane];
            #pragma unroll 4
            for (int k = 0; k < KNB; k++) {
                int j = __shfl_sync(FULLMASK, myidx, k);
                float4 nb = ((const float4*)(pb + (size_t)j * CC))[lane];
                dot4_reduce_store(nb, fq, &S->logit[p][0][i * KNB + k], KT, lane);
            }
            float4 ob = *(const float4*)&S->pcd[p][4 * lane];
            dot4_reduce_store(ob, fq, &S->own[p][0][i], SS, lane);
        }
        __syncthreads();
    }

    // --- softmax + attn_map accumulate: t < 64 owns (p = t>>2, h = t&3) ---
    if (t < PP * HH) {
        const int p = t >> 2, h = t & 3;
        const float inv = 0.17677669529663687f;   // 1/sqrt(32)
        float accA = 0.0f;
        #pragma unroll
        for (int i = 0; i < SS; i++) {
            const float* bki = bk + i * CC + h * DD;
            const float* qp = &S->q[p][h * DD];
            float qb = 0.0f;
            #pragma unroll
            for (int d = 0; d < DD; d++) qb = fmaf(qp[d], bki[d], qb);
            float own = S->own[p][h][i];
            float l[KNB];
            float mx = -1e30f;
            #pragma unroll
            for (int k = 0; k < KNB; k++) {
                l[k] = inv * (S->logit[p][h][i * KNB + k] - own + qb);
                mx = fmaxf(mx, l[k]);
            }
            float se = 0.0f, sl = 0.0f;
            #pragma unroll
            for (int k = 0; k < KNB; k++) {
                float e = __expf(l[k] - mx);
                se += e;
                sl = fmaf(e, l[k], sl);
            }
            accA += sl / se;
        }
        S->attn[p][h] = accA;
    }
    __syncthreads();

    #pragma unroll
    for (int p = 0; p < 8; p++) {
        int pg = half * 8 + p;
        out[((size_t)b * NN + n0 + pg) * CC + col] =
            S->attn[pg][col >> 5] * S->v[pg][col];
    }
}

// ---------------------------------------------------------------------------
extern "C" void kernel_launch(void* const* d_in, const int* in_sizes, int n_in,
                              void* d_out, int out_size) {
    (void)in_sizes; (void)n_in; (void)out_size;
    const float* pcd   = (const float*)d_in[0];
    const float* coord = (const float*)d_in[1];
    const float* Wq    = (const float*)d_in[3];
    const float* bq    = (const float*)d_in[4];
    const float* Wk    = (const float*)d_in[5];
    const float* bk    = (const float*)d_in[6];
    const float* Wv    = (const float*)d_in[7];
    const float* bv    = (const float*)d_in[8];
    float* out = (float*)d_out;

    static_assert(sizeof(AttnSmem) < 100 * 1024, "smem");
    cudaFuncSetAttribute(attn_kernel, cudaFuncAttributeMaxDynamicSharedMemorySize,
                         (int)sizeof(AttnSmem));

    transpose_wk_kernel<<<dim3(CC * CC / 128, SS), 128>>>(Wk);
    knn_kernel<<<BB * NN / 8, 256>>>(coord);
    attn_kernel<<<BB * NN / PP, 256, sizeof(AttnSmem)>>>(pcd, Wq, bq, bk, Wv, bv, out);
}

// round 3
// speedup vs baseline: 2.4583x; 1.1076x over previous
#include <cuda_runtime.h>

#define BB 8
#define NN 2048
#define CC 128
#define HH 4
#define DD 32
#define SS 3
#define KNB 16
#define KT 48
#define PP 16
#define PTP 18    // padded transposed row length (floats)
#define QKP 132

#define FULLMASK 0xffffffffu
typedef unsigned long long ull;

__device__ int   g_knn[BB * NN * KT];
__device__ float g_WkT[SS * CC * CC];

// ---- f32x2 packed-FMA helpers (full fp32 precision, 2 FMA / instr) --------
__device__ __forceinline__ ull pk2(float lo, float hi) {
    ull r; asm("mov.b64 %0, {%1,%2};" : "=l"(r) : "f"(lo), "f"(hi)); return r;
}
__device__ __forceinline__ void fma2(ull& d, ull a, ull b) {
    asm("fma.rn.f32x2 %0, %1, %2, %0;" : "+l"(d) : "l"(a), "l"(b));
}
__device__ __forceinline__ float2 upk2(ull v) {
    float2 f; asm("mov.b64 {%0,%1}, %2;" : "=f"(f.x), "=f"(f.y) : "l"(v)); return f;
}

// ---------------------------------------------------------------------------
// Kernel 0: transpose Wk.  WkT[i][j][c] = Wk[i][c][j]
// ---------------------------------------------------------------------------
__global__ void transpose_wk_kernel(const float* __restrict__ Wk) {
    int i = blockIdx.y;
    int idx = blockIdx.x * blockDim.x + threadIdx.x;
    int c = idx >> 7, j = idx & 127;
    g_WkT[i * CC * CC + j * CC + c] = Wk[i * CC * CC + c * CC + j];
}

// ---------------------------------------------------------------------------
// Kernel 1: exact top-48 kNN per query (no local memory).
// Binary search range initialized from per-lane (min1, min2):
//   hi = warp_max(min2) guarantees >= 64 keys <= hi  (>= KT=48)
//   lo = warp_min(min1) = global minimum
// ---------------------------------------------------------------------------
__global__ __launch_bounds__(256) void knn_kernel(const float* __restrict__ coord) {
    __shared__ float sx[NN], sy[NN], sz[NN], sq[NN];
    __shared__ ull s_buf[8][64];

    const int t = threadIdx.x;
    const int lane = t & 31, w = t >> 5;
    const int b = blockIdx.x / (NN / 8);
    const int n0 = (blockIdx.x % (NN / 8)) * 8;
    const float* cb = coord + (size_t)b * NN * 3;

    for (int j = t; j < NN; j += 256) {
        float x = cb[j * 3], y = cb[j * 3 + 1], z = cb[j * 3 + 2];
        sx[j] = x; sy[j] = y; sz[j] = z;
        sq[j] = fmaf(x, x, fmaf(y, y, z * z));
    }
    __syncthreads();

    const int n = n0 + w;
    const float ox = sx[n], oy = sy[n], oz = sz[n], osq = sq[n];

    unsigned kkey[64];
    unsigned m1 = 0xffffffffu, m2 = 0xffffffffu;
    #pragma unroll
    for (int s = 0; s < 64; s++) {
        int j = lane + (s << 5);
        float dot = fmaf(ox, sx[j], fmaf(oy, sy[j], oz * sz[j]));
        float d = fmaf(-2.0f, dot, osq + sq[j]);   // matches reference formula
        unsigned u = __float_as_uint(d);
        u = (u & 0x80000000u) ? ~u : (u | 0x80000000u);  // monotone total order
        kkey[s] = u;
        if (u < m1) { m2 = m1; m1 = u; } else if (u < m2) { m2 = u; }
    }

    // ---- binary search for threshold T = 48th smallest key ----
    unsigned lo = __reduce_min_sync(FULLMASK, m1);
    unsigned hi = __reduce_max_sync(FULLMASK, m2);
    while (lo < hi) {
        unsigned mid = lo + ((hi - lo) >> 1);
        unsigned c = 0;
        #pragma unroll
        for (int s = 0; s < 64; s++) c += (kkey[s] <= mid) ? 1u : 0u;
        c = __reduce_add_sync(FULLMASK, c);
        if (c >= KT) hi = mid; else lo = mid + 1;
    }
    const unsigned T = lo;

    // ---- collect all candidates with key <= T (ordered by index) ----
    s_buf[w][lane] = ~0ull;
    s_buf[w][lane + 32] = ~0ull;
    __syncwarp();
    int base = 0;
    #pragma unroll
    for (int s = 0; s < 64; s++) {
        bool q = (kkey[s] <= T);
        unsigned m = __ballot_sync(FULLMASK, q);
        if (q) {
            int pos = base + __popc(m & ((1u << lane) - 1u));
            if (pos < 64)
                s_buf[w][pos] = ((ull)kkey[s] << 32) | (unsigned)(lane + (s << 5));
        }
        base += __popc(m);
    }
    __syncwarp();

    // ---- bitonic sort of 64 u64 keys, 2 per lane ----
    ull v0 = s_buf[w][lane];
    ull v1 = s_buf[w][lane + 32];
    #pragma unroll
    for (int k2 = 2; k2 <= 64; k2 <<= 1) {
        #pragma unroll
        for (int j2 = k2 >> 1; j2 > 0; j2 >>= 1) {
            if (j2 == 32) {
                ull a = v0 < v1 ? v0 : v1;
                ull bm = v0 < v1 ? v1 : v0;
                v0 = a; v1 = bm;
            } else {
                bool low = ((lane & j2) == 0);
                bool up0 = ((lane & k2) == 0);
                bool up1 = (((lane + 32) & k2) == 0);
                ull o0 = __shfl_xor_sync(FULLMASK, v0, j2);
                ull o1 = __shfl_xor_sync(FULLMASK, v1, j2);
                bool t0 = (low == up0);
                bool t1 = (low == up1);
                v0 = t0 ? (v0 < o0 ? v0 : o0) : (v0 > o0 ? v0 : o0);
                v1 = t1 ? (v1 < o1 ? v1 : o1) : (v1 > o1 ? v1 : o1);
            }
        }
    }

    int* outp = g_knn + ((size_t)b * NN + n) * KT;
    outp[lane] = (int)(v0 & 0xffffffffu);
    if (lane < KT - 32) outp[32 + lane] = (int)(v1 & 0xffffffffu);
}

// ---------------------------------------------------------------------------
// Kernel 2: fused projections + attention (16 points / 256-thread block).
// pcd and q stored TRANSPOSED in smem ([C][16+pad]) so point-pairs are
// contiguous -> packed f32x2 FMA in the projection GEMMs.
// ---------------------------------------------------------------------------
struct AttnSmem {
    float pcdT[CC][PTP];
    float qT[CC][PTP];
    float v[PP][CC];
    float qk[PP][HH][QKP];
    float logit[PP][HH][KT];
    float own[PP][HH][SS];
    float attn[PP][HH];
};

__device__ __forceinline__ void dot4_reduce_store(
    float4 nb, const float4* fq, float* dst, int strideH, int lane)
{
    float s0 = fmaf(nb.x, fq[0].x, fmaf(nb.y, fq[0].y, fmaf(nb.z, fq[0].z, nb.w * fq[0].w)));
    float s1 = fmaf(nb.x, fq[1].x, fmaf(nb.y, fq[1].y, fmaf(nb.z, fq[1].z, nb.w * fq[1].w)));
    float s2 = fmaf(nb.x, fq[2].x, fmaf(nb.y, fq[2].y, fmaf(nb.z, fq[2].z, nb.w * fq[2].w)));
    float s3 = fmaf(nb.x, fq[3].x, fmaf(nb.y, fq[3].y, fmaf(nb.z, fq[3].z, nb.w * fq[3].w)));
    #pragma unroll
    for (int off = 16; off >= 4; off >>= 1) {
        s0 += __shfl_xor_sync(FULLMASK, s0, off);
        s1 += __shfl_xor_sync(FULLMASK, s1, off);
        s2 += __shfl_xor_sync(FULLMASK, s2, off);
        s3 += __shfl_xor_sync(FULLMASK, s3, off);
    }
    int hsel = (lane >> 2) & 3;
    float v = (hsel == 0) ? s0 : (hsel == 1) ? s1 : (hsel == 2) ? s2 : s3;
    v += __shfl_xor_sync(FULLMASK, v, 1);
    v += __shfl_xor_sync(FULLMASK, v, 2);
    if (lane < 16 && (lane & 3) == 0) dst[hsel * strideH] = v;
}

__global__ __launch_bounds__(256, 3) void attn_kernel(
    const float* __restrict__ pcd,
    const float* __restrict__ Wq, const float* __restrict__ bq,
    const float* __restrict__ bk,
    const float* __restrict__ Wv, const float* __restrict__ bv,
    float* __restrict__ out)
{
    extern __shared__ char smem_raw[];
    AttnSmem* S = (AttnSmem*)smem_raw;

    const int t = threadIdx.x;
    const int lane = t & 31, w = t >> 5;
    const int col = t & 127, half = t >> 7;
    const int b = blockIdx.x / (NN / PP);
    const int n0 = (blockIdx.x % (NN / PP)) * PP;
    const float* pb = pcd + (size_t)b * NN * CC;

    for (int idx = t; idx < PP * CC; idx += 256) {
        int p = idx >> 7, c = idx & 127;
        S->pcdT[c][p] = pb[(size_t)(n0 + p) * CC + c];
    }
    __syncthreads();

    // --- q, v projections with packed f32x2 FMA ---
    {
        ull aq[4] = {0, 0, 0, 0}, av[4] = {0, 0, 0, 0};
        const int pbase = 8 * half;
        #pragma unroll 4
        for (int j = 0; j < CC; j++) {
            float wq = Wq[j * CC + col];
            float wv = Wv[j * CC + col];
            ull w2q = pk2(wq, wq), w2v = pk2(wv, wv);
            const float* xrow = &S->pcdT[j][pbase];
            #pragma unroll
            for (int pp = 0; pp < 4; pp++) {
                ull x = *(const ull*)(xrow + 2 * pp);
                fma2(aq[pp], x, w2q);
                fma2(av[pp], x, w2v);
            }
        }
        float b1 = bq[col], b2 = bv[col];
        #pragma unroll
        for (int pp = 0; pp < 4; pp++) {
            float2 fq = upk2(aq[pp]);
            float2 fv = upk2(av[pp]);
            S->qT[col][pbase + 2 * pp]     = fq.x + b1;
            S->qT[col][pbase + 2 * pp + 1] = fq.y + b1;
            S->v[pbase + 2 * pp][col]     = fv.x + b2;
            S->v[pbase + 2 * pp + 1][col] = fv.y + b2;
        }
    }
    __syncthreads();

    #pragma unroll 1
    for (int i = 0; i < SS; i++) {
        // --- qk projection (f32x2): qk[p][h][col] = sum_{j in head h} q[p][j]*WkT[i][j][col]
        {
            const float* wkt = g_WkT + i * CC * CC + col;
            const int pbase = 8 * half;
            ull acc[4][HH];
            #pragma unroll
            for (int pp = 0; pp < 4; pp++)
                #pragma unroll
                for (int h = 0; h < HH; h++) acc[pp][h] = 0;
            #pragma unroll
            for (int j = 0; j < CC; j++) {
                float wv_ = wkt[j * CC];
                ull w2 = pk2(wv_, wv_);
                const int hh = j >> 5;
                const float* qrow = &S->qT[j][pbase];
                #pragma unroll
                for (int pp = 0; pp < 4; pp++)
                    fma2(acc[pp][hh], *(const ull*)(qrow + 2 * pp), w2);
            }
            #pragma unroll
            for (int pp = 0; pp < 4; pp++)
                #pragma unroll
                for (int h = 0; h < HH; h++) {
                    float2 f = upk2(acc[pp][h]);
                    S->qk[pbase + 2 * pp][h][col]     = f.x;
                    S->qk[pbase + 2 * pp + 1][h][col] = f.y;
                }
        }
        __syncthreads();

        // --- logits: warp w handles points 2w, 2w+1 ---
        #pragma unroll
        for (int pp = 0; pp < 2; pp++) {
            const int p = 2 * w + pp;
            const int* kn = g_knn + ((size_t)b * NN + n0 + p) * KT + i * KNB;
            int myidx = (lane < KNB) ? kn[lane] : 0;
            float4 fq[4];
            #pragma unroll
            for (int h = 0; h < HH; h++)
                fq[h] = *(const float4*)&S->qk[p][h][4 * lane];
            #pragma unroll 4
            for (int k = 0; k < KNB; k++) {
                int j = __shfl_sync(FULLMASK, myidx, k);
                float4 nb = ((const float4*)(pb + (size_t)j * CC))[lane];
                dot4_reduce_store(nb, fq, &S->logit[p][0][i * KNB + k], KT, lane);
            }
            float4 ob;
            ob.x = S->pcdT[4 * lane][p];
            ob.y = S->pcdT[4 * lane + 1][p];
            ob.z = S->pcdT[4 * lane + 2][p];
            ob.w = S->pcdT[4 * lane + 3][p];
            dot4_reduce_store(ob, fq, &S->own[p][0][i], SS, lane);
        }
        __syncthreads();
    }

    // --- softmax + attn_map accumulate: t < 64 owns (p = t>>2, h = t&3) ---
    if (t < PP * HH) {
        const int p = t >> 2, h = t & 3;
        const float inv = 0.17677669529663687f;   // 1/sqrt(32)
        float accA = 0.0f;
        #pragma unroll
        for (int i = 0; i < SS; i++) {
            const float* bki = bk + i * CC + h * DD;
            float qb = 0.0f;
            #pragma unroll
            for (int d = 0; d < DD; d++) qb = fmaf(S->qT[h * DD + d][p], bki[d], qb);
            float own = S->own[p][h][i];
            float l[KNB];
            float mx = -1e30f;
            #pragma unroll
            for (int k = 0; k < KNB; k++) {
                l[k] = inv * (S->logit[p][h][i * KNB + k] - own + qb);
                mx = fmaxf(mx, l[k]);
            }
            float se = 0.0f, sl = 0.0f;
            #pragma unroll
            for (int k = 0; k < KNB; k++) {
                float e = __expf(l[k] - mx);
                se += e;
                sl = fmaf(e, l[k], sl);
            }
            accA += sl / se;
        }
        S->attn[p][h] = accA;
    }
    __syncthreads();

    #pragma unroll
    for (int p = 0; p < 8; p++) {
        int pg = half * 8 + p;
        out[((size_t)b * NN + n0 + pg) * CC + col] =
            S->attn[pg][col >> 5] * S->v[pg][col];
    }
}

// ---------------------------------------------------------------------------
extern "C" void kernel_launch(void* const* d_in, const int* in_sizes, int n_in,
                              void* d_out, int out_size) {
    (void)in_sizes; (void)n_in; (void)out_size;
    const float* pcd   = (const float*)d_in[0];
    const float* coord = (const float*)d_in[1];
    const float* Wq    = (const float*)d_in[3];
    const float* bq    = (const float*)d_in[4];
    const float* Wk    = (const float*)d_in[5];
    const float* bk    = (const float*)d_in[6];
    const float* Wv    = (const float*)d_in[7];
    const float* bv    = (const float*)d_in[8];
    float* out = (float*)d_out;

    static_assert(sizeof(AttnSmem) <= 80 * 1024, "smem");
    cudaFuncSetAttribute(attn_kernel, cudaFuncAttributeMaxDynamicSharedMemorySize,
                         (int)sizeof(AttnSmem));

    // knn first so ncu's fixed-skip capture lands on it (profiling visibility)
    knn_kernel<<<BB * NN / 8, 256>>>(coord);
    transpose_wk_kernel<<<dim3(CC * CC / 128, SS), 128>>>(Wk);
    attn_kernel<<<BB * NN / PP, 256, sizeof(AttnSmem)>>>(pcd, Wq, bq, bk, Wv, bv, out);
}

// round 4
// speedup vs baseline: 3.2917x; 1.3390x over previous
#include <cuda_runtime.h>

#define BB 8
#define NN 2048
#define CC 128
#define HH 4
#define DD 32
#define SS 3
#define KNB 16
#define KT 48
#define PP 16
#define PTP 20    // padded transposed row length (floats, 16B-aligned rows)
#define QKP 132

#define FULLMASK 0xffffffffu
typedef unsigned long long ull;

__device__ int   g_knn[BB * NN * KT];
__device__ float g_WkT[SS * CC * CC];

// ---- f32x2 packed-FMA helpers (full fp32 precision, 2 FMA / instr) --------
__device__ __forceinline__ ull pk2(float lo, float hi) {
    ull r; asm("mov.b64 %0, {%1,%2};" : "=l"(r) : "f"(lo), "f"(hi)); return r;
}
__device__ __forceinline__ void fma2(ull& d, ull a, ull b) {
    asm("fma.rn.f32x2 %0, %1, %2, %0;" : "+l"(d) : "l"(a), "l"(b));
}
__device__ __forceinline__ float2 upk2(ull v) {
    float2 f; asm("mov.b64 {%0,%1}, %2;" : "=f"(f.x), "=f"(f.y) : "l"(v)); return f;
}

// ---------------------------------------------------------------------------
// Kernel 1: exact top-48 kNN per query + folded Wk transpose.
// Binary search with early exit when count == 48 exactly.
// ---------------------------------------------------------------------------
__global__ __launch_bounds__(256) void knn_kernel(const float* __restrict__ coord,
                                                  const float* __restrict__ Wk) {
    __shared__ float sx[NN], sy[NN], sz[NN], sq[NN];
    __shared__ ull s_buf[8][64];

    const int t = threadIdx.x;
    const int lane = t & 31, w = t >> 5;
    const int b = blockIdx.x / (NN / 8);
    const int n0 = (blockIdx.x % (NN / 8)) * 8;
    const float* cb = coord + (size_t)b * NN * 3;

    // folded transpose: 2048 blocks x 24 elements = SS*CC*CC
    if (t < 24) {
        int id = blockIdx.x * 24 + t;
        int i = id >> 14, r = id & 16383;
        int c = r >> 7, j = r & 127;
        g_WkT[i * CC * CC + j * CC + c] = Wk[i * CC * CC + c * CC + j];
    }

    for (int j = t; j < NN; j += 256) {
        float x = cb[j * 3], y = cb[j * 3 + 1], z = cb[j * 3 + 2];
        sx[j] = x; sy[j] = y; sz[j] = z;
        sq[j] = fmaf(x, x, fmaf(y, y, z * z));
    }
    __syncthreads();

    const int n = n0 + w;
    const float ox = sx[n], oy = sy[n], oz = sz[n], osq = sq[n];

    unsigned kkey[64];
    unsigned m1 = 0xffffffffu, m2 = 0xffffffffu;
    #pragma unroll
    for (int s = 0; s < 64; s++) {
        int j = lane + (s << 5);
        float dot = fmaf(ox, sx[j], fmaf(oy, sy[j], oz * sz[j]));
        float d = fmaf(-2.0f, dot, osq + sq[j]);   // matches reference formula
        unsigned u = __float_as_uint(d);
        u = (u & 0x80000000u) ? ~u : (u | 0x80000000u);  // monotone total order
        kkey[s] = u;
        if (u < m1) { m2 = m1; m1 = u; } else if (u < m2) { m2 = u; }
    }

    // ---- binary search for threshold T = 48th smallest key (early exit) ----
    unsigned lo = __reduce_min_sync(FULLMASK, m1);
    unsigned hi = __reduce_max_sync(FULLMASK, m2);   // >= 64 keys <= hi
    unsigned T;
    for (;;) {
        if (lo >= hi) { T = lo; break; }
        unsigned mid = lo + ((hi - lo) >> 1);
        unsigned c = 0;
        #pragma unroll
        for (int s = 0; s < 64; s++) c += (kkey[s] <= mid) ? 1u : 0u;
        c = __reduce_add_sync(FULLMASK, c);
        if (c == KT) { T = mid; break; }     // exactly the 48 smallest
        if (c > KT) hi = mid; else lo = mid + 1;
    }

    // ---- collect all candidates with key <= T (ordered by index) ----
    s_buf[w][lane] = ~0ull;
    s_buf[w][lane + 32] = ~0ull;
    __syncwarp();
    int base = 0;
    #pragma unroll
    for (int s = 0; s < 64; s++) {
        bool q = (kkey[s] <= T);
        unsigned m = __ballot_sync(FULLMASK, q);
        if (q) {
            int pos = base + __popc(m & ((1u << lane) - 1u));
            if (pos < 64)
                s_buf[w][pos] = ((ull)kkey[s] << 32) | (unsigned)(lane + (s << 5));
        }
        base += __popc(m);
    }
    __syncwarp();

    // ---- bitonic sort of 64 u64 keys, 2 per lane ----
    ull v0 = s_buf[w][lane];
    ull v1 = s_buf[w][lane + 32];
    #pragma unroll
    for (int k2 = 2; k2 <= 64; k2 <<= 1) {
        #pragma unroll
        for (int j2 = k2 >> 1; j2 > 0; j2 >>= 1) {
            if (j2 == 32) {
                ull a = v0 < v1 ? v0 : v1;
                ull bm = v0 < v1 ? v1 : v0;
                v0 = a; v1 = bm;
            } else {
                bool low = ((lane & j2) == 0);
                bool up0 = ((lane & k2) == 0);
                bool up1 = (((lane + 32) & k2) == 0);
                ull o0 = __shfl_xor_sync(FULLMASK, v0, j2);
                ull o1 = __shfl_xor_sync(FULLMASK, v1, j2);
                bool t0 = (low == up0);
                bool t1 = (low == up1);
                v0 = t0 ? (v0 < o0 ? v0 : o0) : (v0 > o0 ? v0 : o0);
                v1 = t1 ? (v1 < o1 ? v1 : o1) : (v1 > o1 ? v1 : o1);
            }
        }
    }

    int* outp = g_knn + ((size_t)b * NN + n) * KT;
    outp[lane] = (int)(v0 & 0xffffffffu);
    if (lane < KT - 32) outp[32 + lane] = (int)(v1 & 0xffffffffu);
}

// ---------------------------------------------------------------------------
// Kernel 2: fused projections + attention (16 points / 256-thread block).
// ---------------------------------------------------------------------------
struct AttnSmem {
    float pcdT[CC][PTP];        // pcd transposed  [c][p]
    float qT[CC][PTP];          // q transposed    [c][p]
    float qk[PP][HH][QKP];
    float logit[PP][HH][KT];
    float own[PP][HH][SS];
    float attn[PP][HH];
};

// one-shot 128-dot of nb row against 4 qk head rows (used for own-dot only)
__device__ __forceinline__ void dot4_reduce_store(
    float4 nb, const float4* fq, float* dst, int strideH, int lane)
{
    float s0 = fmaf(nb.x, fq[0].x, fmaf(nb.y, fq[0].y, fmaf(nb.z, fq[0].z, nb.w * fq[0].w)));
    float s1 = fmaf(nb.x, fq[1].x, fmaf(nb.y, fq[1].y, fmaf(nb.z, fq[1].z, nb.w * fq[1].w)));
    float s2 = fmaf(nb.x, fq[2].x, fmaf(nb.y, fq[2].y, fmaf(nb.z, fq[2].z, nb.w * fq[2].w)));
    float s3 = fmaf(nb.x, fq[3].x, fmaf(nb.y, fq[3].y, fmaf(nb.z, fq[3].z, nb.w * fq[3].w)));
    #pragma unroll
    for (int off = 16; off >= 4; off >>= 1) {
        s0 += __shfl_xor_sync(FULLMASK, s0, off);
        s1 += __shfl_xor_sync(FULLMASK, s1, off);
        s2 += __shfl_xor_sync(FULLMASK, s2, off);
        s3 += __shfl_xor_sync(FULLMASK, s3, off);
    }
    int hsel = (lane >> 2) & 3;
    float v = (hsel == 0) ? s0 : (hsel == 1) ? s1 : (hsel == 2) ? s2 : s3;
    v += __shfl_xor_sync(FULLMASK, v, 1);
    v += __shfl_xor_sync(FULLMASK, v, 2);
    if (lane < 16 && (lane & 3) == 0) dst[hsel * strideH] = v;
}

__global__ __launch_bounds__(256, 3) void attn_kernel(
    const float* __restrict__ pcd,
    const float* __restrict__ Wq, const float* __restrict__ bq,
    const float* __restrict__ bk,
    const float* __restrict__ Wv, const float* __restrict__ bv,
    float* __restrict__ out)
{
    extern __shared__ char smem_raw[];
    AttnSmem* S = (AttnSmem*)smem_raw;

    const int t = threadIdx.x;
    const int lane = t & 31, w = t >> 5;
    const int col = t & 127, half = t >> 7;
    const int b = blockIdx.x / (NN / PP);
    const int n0 = (blockIdx.x % (NN / PP)) * PP;
    const float* pb = pcd + (size_t)b * NN * CC;

    for (int idx = t; idx < PP * CC; idx += 256) {
        int p = idx >> 7, c = idx & 127;
        S->pcdT[c][p] = pb[(size_t)(n0 + p) * CC + c];
    }
    __syncthreads();

    const int pbase = 8 * half;

    // --- q projection with packed f32x2 FMA ---
    {
        ull aq[4] = {0, 0, 0, 0};
        #pragma unroll 4
        for (int j = 0; j < CC; j++) {
            float wq = Wq[j * CC + col];
            ull w2q = pk2(wq, wq);
            const ull* xrow = (const ull*)&S->pcdT[j][pbase];
            #pragma unroll
            for (int pp = 0; pp < 4; pp++) fma2(aq[pp], xrow[pp], w2q);
        }
        float b1 = bq[col];
        #pragma unroll
        for (int pp = 0; pp < 4; pp++) {
            float2 fq = upk2(aq[pp]);
            S->qT[col][pbase + 2 * pp]     = fq.x + b1;
            S->qT[col][pbase + 2 * pp + 1] = fq.y + b1;
        }
    }
    __syncthreads();

    const int g  = lane & 7;     // col-group (covers cols 4g + 32m, m=0..3)
    const int kq = lane >> 3;    // neighbor slot within chunk

    #pragma unroll 1
    for (int i = 0; i < SS; i++) {
        // --- qk projection (f32x2) ---
        {
            const float* wkt = g_WkT + i * CC * CC + col;
            ull acc[4][HH];
            #pragma unroll
            for (int pp = 0; pp < 4; pp++)
                #pragma unroll
                for (int h = 0; h < HH; h++) acc[pp][h] = 0;
            #pragma unroll
            for (int j = 0; j < CC; j++) {
                float wv_ = wkt[j * CC];
                ull w2 = pk2(wv_, wv_);
                const int hh = j >> 5;
                const ull* qrow = (const ull*)&S->qT[j][pbase];
                #pragma unroll
                for (int pp = 0; pp < 4; pp++)
                    fma2(acc[pp][hh], qrow[pp], w2);
            }
            #pragma unroll
            for (int pp = 0; pp < 4; pp++)
                #pragma unroll
                for (int h = 0; h < HH; h++) {
                    float2 f = upk2(acc[pp][h]);
                    S->qk[pbase + 2 * pp][h][col]     = f.x;
                    S->qk[pbase + 2 * pp + 1][h][col] = f.y;
                }
        }
        __syncthreads();

        // --- logits: warp w handles points 2w, 2w+1; 4 chunks of 4 neighbors ---
        #pragma unroll
        for (int pp = 0; pp < 2; pp++) {
            const int p = 2 * w + pp;
            const int* kn = g_knn + ((size_t)b * NN + n0 + p) * KT + i * KNB;
            int idxreg = (lane < KNB) ? kn[lane] : 0;

            #pragma unroll
            for (int ch = 0; ch < 4; ch++) {
                int j = __shfl_sync(FULLMASK, idxreg, (ch << 2) | kq);
                const ulonglong2* row = (const ulonglong2*)(pb + (size_t)j * CC);
                ull a0 = 0, a1 = 0, a2 = 0, a3 = 0;
                #pragma unroll
                for (int m = 0; m < 4; m++) {
                    ulonglong2 nb = row[g + (m << 3)];   // cols 4g+32m .. +3
                    const float* qbase = &S->qk[p][0][4 * g + 32 * m];
                    ulonglong2 q0 = *(const ulonglong2*)(qbase);
                    ulonglong2 q1 = *(const ulonglong2*)(qbase + QKP);
                    ulonglong2 q2 = *(const ulonglong2*)(qbase + 2 * QKP);
                    ulonglong2 q3 = *(const ulonglong2*)(qbase + 3 * QKP);
                    fma2(a0, nb.x, q0.x); fma2(a0, nb.y, q0.y);
                    fma2(a1, nb.x, q1.x); fma2(a1, nb.y, q1.y);
                    fma2(a2, nb.x, q2.x); fma2(a2, nb.y, q2.y);
                    fma2(a3, nb.x, q3.x); fma2(a3, nb.y, q3.y);
                }
                float2 f0 = upk2(a0), f1 = upk2(a1), f2 = upk2(a2), f3 = upk2(a3);
                float s0 = f0.x + f0.y, s1 = f1.x + f1.y;
                float s2 = f2.x + f2.y, s3 = f3.x + f3.y;
                #pragma unroll
                for (int off = 1; off <= 4; off <<= 1) {
                    s0 += __shfl_xor_sync(FULLMASK, s0, off);
                    s1 += __shfl_xor_sync(FULLMASK, s1, off);
                    s2 += __shfl_xor_sync(FULLMASK, s2, off);
                    s3 += __shfl_xor_sync(FULLMASK, s3, off);
                }
                if (g < 4) {
                    float v01 = (g & 1) ? s1 : s0;
                    float v23 = (g & 1) ? s3 : s2;
                    float val = (g & 2) ? v23 : v01;
                    S->logit[p][g][i * KNB + (ch << 2) + kq] = val;
                }
            }

            // own-dot via one-shot reduce
            {
                float4 fq[4];
                #pragma unroll
                for (int h = 0; h < HH; h++)
                    fq[h] = *(const float4*)&S->qk[p][h][4 * lane];
                float4 ob = ((const float4*)(pb + (size_t)(n0 + p) * CC))[lane];
                dot4_reduce_store(ob, fq, &S->own[p][0][i], SS, lane);
            }
        }
        __syncthreads();
    }

    // --- softmax + attn_map accumulate: t < 64 owns (p = t>>2, h = t&3) ---
    if (t < PP * HH) {
        const int p = t >> 2, h = t & 3;
        const float inv = 0.17677669529663687f;   // 1/sqrt(32)
        float accA = 0.0f;
        #pragma unroll
        for (int i = 0; i < SS; i++) {
            const float* bki = bk + i * CC + h * DD;
            float qb = 0.0f;
            #pragma unroll
            for (int d = 0; d < DD; d++) qb = fmaf(S->qT[h * DD + d][p], bki[d], qb);
            float own = S->own[p][h][i];
            float l[KNB];
            float mx = -1e30f;
            #pragma unroll
            for (int k = 0; k < KNB; k++) {
                l[k] = inv * (S->logit[p][h][i * KNB + k] - own + qb);
                mx = fmaxf(mx, l[k]);
            }
            float se = 0.0f, sl = 0.0f;
            #pragma unroll
            for (int k = 0; k < KNB; k++) {
                float e = __expf(l[k] - mx);
                se += e;
                sl = fmaf(e, l[k], sl);
            }
            accA += sl / se;
        }
        S->attn[p][h] = accA;
    }
    __syncthreads();

    // --- v projection fused with output write ---
    {
        ull av[4] = {0, 0, 0, 0};
        #pragma unroll 4
        for (int j = 0; j < CC; j++) {
            float wv = Wv[j * CC + col];
            ull w2v = pk2(wv, wv);
            const ull* xrow = (const ull*)&S->pcdT[j][pbase];
            #pragma unroll
            for (int pp = 0; pp < 4; pp++) fma2(av[pp], xrow[pp], w2v);
        }
        float b2 = bv[col];
        const int hsel = col >> 5;
        #pragma unroll
        for (int pp = 0; pp < 4; pp++) {
            float2 fv = upk2(av[pp]);
            int p0 = pbase + 2 * pp, p1 = p0 + 1;
            out[((size_t)b * NN + n0 + p0) * CC + col] = S->attn[p0][hsel] * (fv.x + b2);
            out[((size_t)b * NN + n0 + p1) * CC + col] = S->attn[p1][hsel] * (fv.y + b2);
        }
    }
}

// ---------------------------------------------------------------------------
extern "C" void kernel_launch(void* const* d_in, const int* in_sizes, int n_in,
                              void* d_out, int out_size) {
    (void)in_sizes; (void)n_in; (void)out_size;
    const float* pcd   = (const float*)d_in[0];
    const float* coord = (const float*)d_in[1];
    const float* Wq    = (const float*)d_in[3];
    const float* bq    = (const float*)d_in[4];
    const float* Wk    = (const float*)d_in[5];
    const float* bk    = (const float*)d_in[6];
    const float* Wv    = (const float*)d_in[7];
    const float* bv    = (const float*)d_in[8];
    float* out = (float*)d_out;

    static_assert(sizeof(AttnSmem) <= 70 * 1024, "smem");
    cudaFuncSetAttribute(attn_kernel, cudaFuncAttributeMaxDynamicSharedMemorySize,
                         (int)sizeof(AttnSmem));

    knn_kernel<<<BB * NN / 8, 256>>>(coord, Wk);
    attn_kernel<<<BB * NN / PP, 256, sizeof(AttnSmem)>>>(pcd, Wq, bq, bk, Wv, bv, out);
}